// round 15
// baseline (speedup 1.0000x reference)
#include <cuda_runtime.h>
#include <cstdint>

typedef unsigned long long ull;
typedef unsigned int uint;

constexpr int BH  = 8;
constexpr int T   = 512;
constexpr int D   = 64;
constexpr int HID = 128;
constexpr int NP  = HID / 2;   // 64 channel pairs

// pair-major scratch: [bh][pair][T] as 64-bit channel pairs, |w2| folded, b1 folded into k
__device__ ull g_qsp[BH * NP * T];   // 2 MB
__device__ ull g_ksp[BH * NP * T];   // 2 MB

// ---------------- K1: projections (|w2| and b1 folded) + pair-major transpose ----------------
// R4-proven: 64 rows per CTA, grid (8, BH, 2), 256 threads.
constexpr int SM1_BYTES = 32768 + 64 * 68 * 4;   // 50176

__global__ __launch_bounds__(256) void k1_proj(
    const float* __restrict__ q, const float* __restrict__ k,
    const float* __restrict__ W1, const float* __restrict__ b1,
    const float* __restrict__ W2)
{
    extern __shared__ char sm1[];
    ull*   sWp = (ull*)sm1;               // [D][NP]
    float* sR  = (float*)(sm1 + 32768);   // [64][68]
    ull*   sT  = (ull*)sm1;               // [64][65] (aliased after sync)

    int tid = threadIdx.x;
    int bh  = blockIdx.y;
    int r0  = blockIdx.x * 64;
    int isk = blockIdx.z;

    const float* src  = isk ? k : q;
    const float* wsrc = W1 + (isk ? D * HID : 0);

    for (int idx = tid; idx < D * HID / 4; idx += 256) {
        int d = idx >> 5, g = idx & 31;
        *(float4*)&sWp[d * NP + 2 * g] = *(const float4*)&wsrc[d * HID + g * 4];
    }
    for (int idx = tid; idx < 64 * D / 4; idx += 256) {
        int r = idx >> 4, c = idx & 15;
        *(float4*)&sR[r * 68 + c * 4] = *(const float4*)&src[(bh * T + r0 + r) * D + c * 4];
    }
    __syncthreads();

    int ti = tid >> 4;      // 16 groups x 4 rows
    int tc = tid & 15;      // pairs {tc, tc+16, tc+32, tc+48}

    ull acc[4][4];
    #pragma unroll
    for (int a = 0; a < 4; a++)
        #pragma unroll
        for (int b = 0; b < 4; b++) acc[a][b] = 0ull;

    #pragma unroll 2
    for (int d = 0; d < D; d++) {
        ull w0 = sWp[d * NP + tc];
        ull w1 = sWp[d * NP + tc + 16];
        ull w2 = sWp[d * NP + tc + 32];
        ull w3 = sWp[d * NP + tc + 48];
        #pragma unroll
        for (int ii = 0; ii < 4; ii++) {
            float a = sR[(ti * 4 + ii) * 68 + d];
            ull ap; asm("mov.b64 %0, {%1,%1};" : "=l"(ap) : "f"(a));
            asm("fma.rn.f32x2 %0, %1, %2, %0;" : "+l"(acc[ii][0]) : "l"(ap), "l"(w0));
            asm("fma.rn.f32x2 %0, %1, %2, %0;" : "+l"(acc[ii][1]) : "l"(ap), "l"(w1));
            asm("fma.rn.f32x2 %0, %1, %2, %0;" : "+l"(acc[ii][2]) : "l"(ap), "l"(w2));
            asm("fma.rn.f32x2 %0, %1, %2, %0;" : "+l"(acc[ii][3]) : "l"(ap), "l"(w3));
        }
    }

    // per-channel params: gg = |w2_c|, bb = b1 (k side only); channels 2*(tc+16m)+e
    float gg[8], bb[8];
    #pragma unroll
    for (int m = 0; m < 4; m++)
        #pragma unroll
        for (int e = 0; e < 2; e++) {
            int ch = 2 * (tc + 16 * m) + e;
            gg[2 * m + e] = fabsf(W2[ch]);
            bb[2 * m + e] = isk ? b1[ch] : 0.0f;
        }

    __syncthreads();   // sW/sR dead; sT may alias now

    #pragma unroll
    for (int ii = 0; ii < 4; ii++) {
        #pragma unroll
        for (int m = 0; m < 4; m++) {
            float lo = __uint_as_float((uint)(acc[ii][m] & 0xffffffffu));
            float hi = __uint_as_float((uint)(acc[ii][m] >> 32));
            float o0 = gg[2 * m]     * (lo + bb[2 * m]);
            float o1 = gg[2 * m + 1] * (hi + bb[2 * m + 1]);
            ull pr = (ull)__float_as_uint(o0) | ((ull)__float_as_uint(o1) << 32);
            sT[(ti * 4 + ii) * 65 + tc + 16 * m] = pr;
        }
    }
    __syncthreads();

    // coalesced pair-major writeout
    ull* dst = (isk ? g_ksp : g_qsp) + (size_t)bh * NP * T;
    for (int idx = tid; idx < 64 * NP; idx += 256) {
        int r = idx & 63, p = idx >> 6;
        dst[p * T + r0 + r] = sT[r * 65 + p];
    }
}

// ---------------- K3: pairwise relu main kernel ----------------
// R14 config (1024 thr, 64x256 tile, split-half smem) + warp-staggered p phases.
constexpr int SM3_BYTES = 2048 * 8 * 2 + 8192 * 8 * 2 + NP * 8;   // 164352

#define K3_BODY(p) do {                                                     \
    ulonglong2 qv01 = *(const ulonglong2*)(qlo + (p) * 32);                 \
    ulonglong2 qv23 = *(const ulonglong2*)(qhi + (p) * 32);                 \
    ulonglong2 kv01 = *(const ulonglong2*)(klo + (p) * 128);                \
    ulonglong2 kv23 = *(const ulonglong2*)(khi + (p) * 128);                \
    ull qv[4] = { qv01.x, qv01.y, qv23.x, qv23.y };                         \
    ull kv[4] = { kv01.x, kv01.y, kv23.x, kv23.y };                         \
    ull sg = ssg[(p)];                                                      \
    _Pragma("unroll")                                                       \
    for (int r = 0; r < 4; r++)                                             \
        _Pragma("unroll")                                                   \
        for (int s = 0; s < 4; s++) {                                       \
            asm("{\n\t"                                                     \
                ".reg .b64 t;\n\t"                                          \
                ".reg .f32 lo, hi;\n\t"                                     \
                "add.rn.f32x2 t, %1, %2;\n\t"                               \
                "mov.b64 {lo, hi}, t;\n\t"                                  \
                "max.f32 lo, lo, 0f00000000;\n\t"                           \
                "max.f32 hi, hi, 0f00000000;\n\t"                           \
                "mov.b64 t, {lo, hi};\n\t"                                  \
                "fma.rn.f32x2 %0, t, %3, %0;\n\t"                           \
                "}"                                                         \
                : "+l"(acc[r][s]) : "l"(qv[r]), "l"(kv[s]), "l"(sg));       \
        }                                                                   \
} while (0)

__global__ __launch_bounds__(1024, 1) void k3_main(
    const float* __restrict__ W2, const float* __restrict__ b2,
    float* __restrict__ out)
{
    extern __shared__ ull sm3[];
    ull* sq_lo = sm3;                 // [p][g<16] rows 4g+0,1   (2048 ull)
    ull* sq_hi = sq_lo + 2048;        // [p][g<16] rows 4g+2,3
    ull* sk_lo = sq_hi + 2048;        // [p][g<64] cols 4g+0,1   (8192 ull)
    ull* sk_hi = sk_lo + 8192;        // [p][g<64] cols 4g+2,3
    ull* ssg   = sk_hi + 8192;        // [64] packed (+-1.0f, +-1.0f)

    int tid = threadIdx.x;
    int bx  = blockIdx.x;
    int bh  = bx >> 4;
    int it  = (bx >> 1) & 7;
    int jt  = bx & 1;
    int i0  = it * 64, j0 = jt * 256;

    const ull* gq = g_qsp + (size_t)bh * NP * T;
    const ull* gk = g_ksp + (size_t)bh * NP * T;

    // fills: gmem-coalesced reads; split-half smem writes (conflict-free)
    for (int idx = tid; idx < NP * 64; idx += 1024) {
        int p = idx >> 6, r = idx & 63;
        int g = r >> 2, h = (r >> 1) & 1, c = r & 1;
        (h ? sq_hi : sq_lo)[(p * 16 + g) * 2 + c] = gq[p * T + i0 + r];
    }
    for (int idx = tid; idx < NP * 256; idx += 1024) {
        int p = idx >> 8, j = idx & 255;
        int g = j >> 2, h = (j >> 1) & 1, c = j & 1;
        (h ? sk_hi : sk_lo)[(p * 64 + g) * 2 + c] = gk[p * T + j0 + j];
    }
    if (tid < NP) {
        uint s0 = 0x3F800000u | (__float_as_uint(W2[2 * tid])     & 0x80000000u);
        uint s1 = 0x3F800000u | (__float_as_uint(W2[2 * tid + 1]) & 0x80000000u);
        ssg[tid] = (ull)s0 | ((ull)s1 << 32);
    }
    __syncthreads();

    int warp = tid >> 5, lane = tid & 31;
    int wi = warp >> 3, wj = warp & 7;   // 4x8 warps: warp tile 16x32
    int li = lane >> 3, lj = lane & 7;   // lanes: 4 row-groups x 8 col-groups

    int qg = wi * 4 + li;                // q group (rows 4qg..4qg+3)
    int kg = wj * 8 + lj;                // k group (cols 4kg..4kg+3)

    const ull* qlo = sq_lo + qg * 2;     // + p*32
    const ull* qhi = sq_hi + qg * 2;
    const ull* klo = sk_lo + kg * 2;     // + p*128
    const ull* khi = sk_hi + kg * 2;

    ull acc[4][4];
    #pragma unroll
    for (int r = 0; r < 4; r++)
        #pragma unroll
        for (int s = 0; s < 4; s++) acc[r][s] = 0ull;

    // stagger start phase per warp (8 phases per SMSP: SMSP = warp & 3, phase = warp >> 2)
    int off = ((warp >> 2) & 7) * 8;

    #pragma unroll 2
    for (int p = off; p < NP; p++) K3_BODY(p);
    #pragma unroll 2
    for (int p = 0; p < off; p++) K3_BODY(p);

    float b2v = b2[0];
    // rows: i0 + 4*qg + r; cols: j0 + 4*kg + s (consecutive -> STG.128)
    float* ob = out + (size_t)(bh * T + i0 + 4 * qg) * T + j0 + 4 * kg;
    #pragma unroll
    for (int r = 0; r < 4; r++) {
        float4 v;
        float* vp = (float*)&v;
        #pragma unroll
        for (int s = 0; s < 4; s++) {
            float lo = __uint_as_float((uint)(acc[r][s] & 0xffffffffu));
            float hi = __uint_as_float((uint)(acc[r][s] >> 32));
            vp[s] = lo + hi + b2v;
        }
        *(float4*)(ob + (size_t)r * T) = v;
    }
}

// ---------------- launch ----------------
extern "C" void kernel_launch(void* const* d_in, const int* in_sizes, int n_in,
                              void* d_out, int out_size) {
    const float* q  = (const float*)d_in[0];
    const float* k  = (const float*)d_in[1];
    const float* W1 = (const float*)d_in[2];
    const float* b1 = (const float*)d_in[3];
    const float* W2 = (const float*)d_in[4];
    const float* b2 = (const float*)d_in[5];
    float* out = (float*)d_out;

    cudaFuncSetAttribute(k1_proj, cudaFuncAttributeMaxDynamicSharedMemorySize, SM1_BYTES);
    cudaFuncSetAttribute(k3_main, cudaFuncAttributeMaxDynamicSharedMemorySize, SM3_BYTES);

    k1_proj<<<dim3(8, BH, 2), 256, SM1_BYTES>>>(q, k, W1, b1, W2);
    k3_main<<<128, 1024, SM3_BYTES>>>(W2, b2, out);
}

// round 16
// speedup vs baseline: 1.2070x; 1.2070x over previous
#include <cuda_runtime.h>
#include <cstdint>

typedef unsigned long long ull;
typedef unsigned int uint;

constexpr int BH  = 8;
constexpr int T   = 512;
constexpr int D   = 64;
constexpr int HID = 128;
constexpr int NP  = HID / 2;   // 64 channel pairs

// pair-major scratch: [bh][pair][T] as 64-bit channel pairs, |w2| folded, b1 folded into k
__device__ ull g_qsp[BH * NP * T];   // 2 MB
__device__ ull g_ksp[BH * NP * T];   // 2 MB

// ---------------- K1: projections (|w2| and b1 folded), channel-split ----------------
// Each CTA: 64 rows x 32 pairs (half the channels). Grid (8, BH, 4): z = isk*2 + ch.
// smem: sWp [64][32] ull (16KB) | sR [64][68] float (17.4KB); sT [64][33] ull aliases at 0.
constexpr int SM1_BYTES = 16384 + 64 * 68 * 4;   // 33792

__global__ __launch_bounds__(256) void k1_proj(
    const float* __restrict__ q, const float* __restrict__ k,
    const float* __restrict__ W1, const float* __restrict__ b1,
    const float* __restrict__ W2)
{
    extern __shared__ char sm1[];
    ull*   sWp = (ull*)sm1;               // [D][32]
    float* sR  = (float*)(sm1 + 16384);   // [64][68]
    ull*   sT  = (ull*)sm1;               // [64][33] (aliased after sync)

    int tid = threadIdx.x;
    int bh  = blockIdx.y;
    int r0  = blockIdx.x * 64;
    int isk = blockIdx.z >> 1;
    int ch  = blockIdx.z & 1;             // channel half: pairs [ch*32, ch*32+32)

    const float* src  = isk ? k : q;
    const float* wsrc = W1 + (isk ? D * HID : 0) + ch * 64;   // 64 floats = 32 pairs

    // weight half fill: row d has 64 contiguous floats
    for (int idx = tid; idx < D * 64 / 4; idx += 256) {
        int d = idx >> 4, g = idx & 15;
        *(float4*)&sWp[d * 32 + 2 * g] = *(const float4*)&wsrc[d * HID + g * 4];
    }
    for (int idx = tid; idx < 64 * D / 4; idx += 256) {
        int r = idx >> 4, c = idx & 15;
        *(float4*)&sR[r * 68 + c * 4] = *(const float4*)&src[(bh * T + r0 + r) * D + c * 4];
    }
    __syncthreads();

    int ti = tid >> 4;      // 16 groups x 4 rows
    int tc = tid & 15;      // local pairs {tc, tc+16}

    ull acc[4][2];
    #pragma unroll
    for (int a = 0; a < 4; a++) { acc[a][0] = 0ull; acc[a][1] = 0ull; }

    #pragma unroll 4
    for (int d = 0; d < D; d++) {
        ull w0 = sWp[d * 32 + tc];
        ull w1 = sWp[d * 32 + tc + 16];
        #pragma unroll
        for (int ii = 0; ii < 4; ii++) {
            float a = sR[(ti * 4 + ii) * 68 + d];
            ull ap; asm("mov.b64 %0, {%1,%1};" : "=l"(ap) : "f"(a));
            asm("fma.rn.f32x2 %0, %1, %2, %0;" : "+l"(acc[ii][0]) : "l"(ap), "l"(w0));
            asm("fma.rn.f32x2 %0, %1, %2, %0;" : "+l"(acc[ii][1]) : "l"(ap), "l"(w1));
        }
    }

    // per-channel params: gg = |w2_c|, bb = b1 (k side only); global channel 2*(ch*32+lp)+e
    float gg[4], bb[4];
    #pragma unroll
    for (int m = 0; m < 2; m++)
        #pragma unroll
        for (int e = 0; e < 2; e++) {
            int chan = 2 * (ch * 32 + tc + 16 * m) + e;
            gg[2 * m + e] = fabsf(W2[chan]);
            bb[2 * m + e] = isk ? b1[chan] : 0.0f;
        }

    __syncthreads();   // sWp/sR dead; sT may alias now

    #pragma unroll
    for (int ii = 0; ii < 4; ii++) {
        #pragma unroll
        for (int m = 0; m < 2; m++) {
            float lo = __uint_as_float((uint)(acc[ii][m] & 0xffffffffu));
            float hi = __uint_as_float((uint)(acc[ii][m] >> 32));
            float o0 = gg[2 * m]     * (lo + bb[2 * m]);
            float o1 = gg[2 * m + 1] * (hi + bb[2 * m + 1]);
            ull pr = (ull)__float_as_uint(o0) | ((ull)__float_as_uint(o1) << 32);
            sT[(ti * 4 + ii) * 33 + tc + 16 * m] = pr;
        }
    }
    __syncthreads();

    // coalesced pair-major writeout (32 local pairs)
    ull* dst = (isk ? g_ksp : g_qsp) + (size_t)bh * NP * T;
    for (int idx = tid; idx < 64 * 32; idx += 256) {
        int r = idx & 63, p = idx >> 6;
        dst[(ch * 32 + p) * T + r0 + r] = sT[r * 33 + p];
    }
}

// ---------------- K3: pairwise relu main kernel (R14 proven, byte-identical) ----------------
// 1024 thr, 64x256 tile, split-half smem layout (conflict-free LDS.128).
constexpr int SM3_BYTES = 2048 * 8 * 2 + 8192 * 8 * 2 + NP * 8;   // 164352

__global__ __launch_bounds__(1024, 1) void k3_main(
    const float* __restrict__ W2, const float* __restrict__ b2,
    float* __restrict__ out)
{
    extern __shared__ ull sm3[];
    ull* sq_lo = sm3;                 // [p][g<16] rows 4g+0,1   (2048 ull)
    ull* sq_hi = sq_lo + 2048;        // [p][g<16] rows 4g+2,3
    ull* sk_lo = sq_hi + 2048;        // [p][g<64] cols 4g+0,1   (8192 ull)
    ull* sk_hi = sk_lo + 8192;        // [p][g<64] cols 4g+2,3
    ull* ssg   = sk_hi + 8192;        // [64] packed (+-1.0f, +-1.0f)

    int tid = threadIdx.x;
    int bx  = blockIdx.x;
    int bh  = bx >> 4;
    int it  = (bx >> 1) & 7;
    int jt  = bx & 1;
    int i0  = it * 64, j0 = jt * 256;

    const ull* gq = g_qsp + (size_t)bh * NP * T;
    const ull* gk = g_ksp + (size_t)bh * NP * T;

    // fills: gmem-coalesced reads; split-half smem writes (conflict-free)
    for (int idx = tid; idx < NP * 64; idx += 1024) {
        int p = idx >> 6, r = idx & 63;
        int g = r >> 2, h = (r >> 1) & 1, c = r & 1;
        (h ? sq_hi : sq_lo)[(p * 16 + g) * 2 + c] = gq[p * T + i0 + r];
    }
    for (int idx = tid; idx < NP * 256; idx += 1024) {
        int p = idx >> 8, j = idx & 255;
        int g = j >> 2, h = (j >> 1) & 1, c = j & 1;
        (h ? sk_hi : sk_lo)[(p * 64 + g) * 2 + c] = gk[p * T + j0 + j];
    }
    if (tid < NP) {
        uint s0 = 0x3F800000u | (__float_as_uint(W2[2 * tid])     & 0x80000000u);
        uint s1 = 0x3F800000u | (__float_as_uint(W2[2 * tid + 1]) & 0x80000000u);
        ssg[tid] = (ull)s0 | ((ull)s1 << 32);
    }
    __syncthreads();

    int warp = tid >> 5, lane = tid & 31;
    int wi = warp >> 3, wj = warp & 7;   // 4x8 warps: warp tile 16x32
    int li = lane >> 3, lj = lane & 7;   // lanes: 4 row-groups x 8 col-groups

    int qg = wi * 4 + li;                // q group (rows 4qg..4qg+3)
    int kg = wj * 8 + lj;                // k group (cols 4kg..4kg+3)

    const ull* qlo = sq_lo + qg * 2;     // + p*32
    const ull* qhi = sq_hi + qg * 2;
    const ull* klo = sk_lo + kg * 2;     // + p*128
    const ull* khi = sk_hi + kg * 2;

    ull acc[4][4];
    #pragma unroll
    for (int r = 0; r < 4; r++)
        #pragma unroll
        for (int s = 0; s < 4; s++) acc[r][s] = 0ull;

    #pragma unroll 1
    for (int p = 0; p < NP; p++) {
        ulonglong2 qv01 = *(const ulonglong2*)(qlo + p * 32);    // rows 4li+0,1
        ulonglong2 qv23 = *(const ulonglong2*)(qhi + p * 32);    // rows 4li+2,3
        ulonglong2 kv01 = *(const ulonglong2*)(klo + p * 128);   // cols 4lj+0,1
        ulonglong2 kv23 = *(const ulonglong2*)(khi + p * 128);   // cols 4lj+2,3
        ull qv[4] = { qv01.x, qv01.y, qv23.x, qv23.y };
        ull kv[4] = { kv01.x, kv01.y, kv23.x, kv23.y };
        ull sg = ssg[p];
        #pragma unroll
        for (int r = 0; r < 4; r++)
            #pragma unroll
            for (int s = 0; s < 4; s++) {
                // u = q+k (packed); relu halves (FMNMX, alu pipe); acc += u * (+-1) (packed)
                asm("{\n\t"
                    ".reg .b64 t;\n\t"
                    ".reg .f32 lo, hi;\n\t"
                    "add.rn.f32x2 t, %1, %2;\n\t"
                    "mov.b64 {lo, hi}, t;\n\t"
                    "max.f32 lo, lo, 0f00000000;\n\t"
                    "max.f32 hi, hi, 0f00000000;\n\t"
                    "mov.b64 t, {lo, hi};\n\t"
                    "fma.rn.f32x2 %0, t, %3, %0;\n\t"
                    "}"
                    : "+l"(acc[r][s]) : "l"(qv[r]), "l"(kv[s]), "l"(sg));
            }
    }

    float b2v = b2[0];
    // rows: i0 + 4*qg + r; cols: j0 + 4*kg + s (consecutive -> STG.128)
    float* ob = out + (size_t)(bh * T + i0 + 4 * qg) * T + j0 + 4 * kg;
    #pragma unroll
    for (int r = 0; r < 4; r++) {
        float4 v;
        float* vp = (float*)&v;
        #pragma unroll
        for (int s = 0; s < 4; s++) {
            float lo = __uint_as_float((uint)(acc[r][s] & 0xffffffffu));
            float hi = __uint_as_float((uint)(acc[r][s] >> 32));
            vp[s] = lo + hi + b2v;
        }
        *(float4*)(ob + (size_t)r * T) = v;
    }
}

// ---------------- launch ----------------
extern "C" void kernel_launch(void* const* d_in, const int* in_sizes, int n_in,
                              void* d_out, int out_size) {
    const float* q  = (const float*)d_in[0];
    const float* k  = (const float*)d_in[1];
    const float* W1 = (const float*)d_in[2];
    const float* b1 = (const float*)d_in[3];
    const float* W2 = (const float*)d_in[4];
    const float* b2 = (const float*)d_in[5];
    float* out = (float*)d_out;

    cudaFuncSetAttribute(k1_proj, cudaFuncAttributeMaxDynamicSharedMemorySize, SM1_BYTES);
    cudaFuncSetAttribute(k3_main, cudaFuncAttributeMaxDynamicSharedMemorySize, SM3_BYTES);

    k1_proj<<<dim3(8, BH, 4), 256, SM1_BYTES>>>(q, k, W1, b1, W2);
    k3_main<<<128, 1024, SM3_BYTES>>>(W2, b2, out);
}

// round 17
// speedup vs baseline: 1.2330x; 1.0216x over previous
#include <cuda_runtime.h>
#include <cstdint>

typedef unsigned long long ull;
typedef unsigned int uint;

constexpr int BH  = 8;
constexpr int T   = 512;
constexpr int D   = 64;
constexpr int HID = 128;
constexpr int NP  = HID / 2;   // 64 channel pairs

// pair-major scratch: [bh][pair][T]; channels PERMUTED (positives first), 0.5*|w2| folded,
// b1 folded into k side. Linear rank-1 sums in g_Lq/g_Lk.
__device__ ull   g_qsp[BH * NP * T];   // 2 MB
__device__ ull   g_ksp[BH * NP * T];   // 2 MB
__device__ float g_Lq[BH * T];         // sum_c sigma_c * qs_c
__device__ float g_Lk[BH * T];         // sum_c sigma_c * ks_c

// ---------------- K1: projections + sign-permutation + linear row sums ----------------
// smem: sWp [64][64] ull (32KB) | sR [64][68] float (17.4KB) | sPi[128] + sCnt[4] ints.
// sT [64][65] ull aliases at offset 0 after the FMA loop.
constexpr int SM1_BYTES = 32768 + 64 * 68 * 4 + 128 * 4 + 16 * 4;   // 50752

__global__ __launch_bounds__(256) void k1_proj(
    const float* __restrict__ q, const float* __restrict__ k,
    const float* __restrict__ W1, const float* __restrict__ b1,
    const float* __restrict__ W2)
{
    extern __shared__ char sm1[];
    ull*   sWp  = (ull*)sm1;                       // [D][NP]
    float* sR   = (float*)(sm1 + 32768);           // [64][68]
    int*   sPi  = (int*)(sm1 + 32768 + 64*68*4);   // [128]
    int*   sCnt = sPi + 128;                        // [4]
    ull*   sT   = (ull*)sm1;                        // [64][65] aliased later
    uint*  sT32 = (uint*)sm1;                       // rows stride 130 u32

    int tid = threadIdx.x;
    int bh  = blockIdx.y;
    int r0  = blockIdx.x * 64;
    int isk = blockIdx.z;

    const float* src  = isk ? k : q;
    const float* wsrc = W1 + (isk ? D * HID : 0);

    // sign ballot (warps 0-3 hold channels 0..127)
    bool mypos = false; uint mybal = 0;
    int wrp = tid >> 5, lane = tid & 31;
    if (tid < 128) {
        uint wb = __float_as_uint(W2[tid]);
        mypos = !(wb >> 31);
        mybal = __ballot_sync(0xffffffffu, mypos);
        if (lane == 0) sCnt[wrp] = __popc(mybal);
    }

    for (int idx = tid; idx < D * HID / 4; idx += 256) {
        int d = idx >> 5, g = idx & 31;
        *(float4*)&sWp[d * NP + 2 * g] = *(const float4*)&wsrc[d * HID + g * 4];
    }
    for (int idx = tid; idx < 64 * D / 4; idx += 256) {
        int r = idx >> 4, c = idx & 15;
        *(float4*)&sR[r * 68 + c * 4] = *(const float4*)&src[(bh * T + r0 + r) * D + c * 4];
    }
    __syncthreads();

    // permutation: positives -> [0,NPOS), negatives -> [NPOS,128), order-stable
    if (tid < 128) {
        int NPOS = sCnt[0] + sCnt[1] + sCnt[2] + sCnt[3];
        int po = 0, no = 0;
        for (int ww = 0; ww < wrp; ww++) { po += sCnt[ww]; no += 32 - sCnt[ww]; }
        int rp = __popc(mybal & ((1u << lane) - 1));
        int rn = lane - rp;
        sPi[tid] = mypos ? (po + rp) : (NPOS + no + rn);
    }

    int ti = tid >> 4;      // 16 groups x 4 rows
    int tc = tid & 15;      // pairs {tc, tc+16, tc+32, tc+48}

    ull acc[4][4];
    #pragma unroll
    for (int a = 0; a < 4; a++)
        #pragma unroll
        for (int b = 0; b < 4; b++) acc[a][b] = 0ull;

    #pragma unroll 2
    for (int d = 0; d < D; d++) {
        ull w0 = sWp[d * NP + tc];
        ull w1 = sWp[d * NP + tc + 16];
        ull w2 = sWp[d * NP + tc + 32];
        ull w3 = sWp[d * NP + tc + 48];
        #pragma unroll
        for (int ii = 0; ii < 4; ii++) {
            float a = sR[(ti * 4 + ii) * 68 + d];
            ull ap; asm("mov.b64 %0, {%1,%1};" : "=l"(ap) : "f"(a));
            asm("fma.rn.f32x2 %0, %1, %2, %0;" : "+l"(acc[ii][0]) : "l"(ap), "l"(w0));
            asm("fma.rn.f32x2 %0, %1, %2, %0;" : "+l"(acc[ii][1]) : "l"(ap), "l"(w1));
            asm("fma.rn.f32x2 %0, %1, %2, %0;" : "+l"(acc[ii][2]) : "l"(ap), "l"(w2));
            asm("fma.rn.f32x2 %0, %1, %2, %0;" : "+l"(acc[ii][3]) : "l"(ap), "l"(w3));
        }
    }

    // per-channel params: gg = 0.5*|w2|, bb = b1 (k side), sigma sign, target slot
    float gg[8], bb[8], sgf[8]; int pi[8];
    #pragma unroll
    for (int m = 0; m < 4; m++)
        #pragma unroll
        for (int e = 0; e < 2; e++) {
            int ch = 2 * (tc + 16 * m) + e;
            float w = W2[ch];
            gg[2 * m + e] = 0.5f * fabsf(w);
            bb[2 * m + e] = isk ? b1[ch] : 0.0f;
            sgf[2 * m + e] = (__float_as_uint(w) >> 31) ? -1.0f : 1.0f;
            pi[2 * m + e] = sPi[ch];
        }

    __syncthreads();   // sWp/sR dead; sT may alias now

    float ls[4];
    #pragma unroll
    for (int ii = 0; ii < 4; ii++) {
        int row = ti * 4 + ii;
        float s = 0.0f;
        #pragma unroll
        for (int m = 0; m < 4; m++) {
            float lo = __uint_as_float((uint)(acc[ii][m] & 0xffffffffu));
            float hi = __uint_as_float((uint)(acc[ii][m] >> 32));
            float o0 = gg[2 * m]     * (lo + bb[2 * m]);
            float o1 = gg[2 * m + 1] * (hi + bb[2 * m + 1]);
            sT32[row * 130 + pi[2 * m]]     = __float_as_uint(o0);
            sT32[row * 130 + pi[2 * m + 1]] = __float_as_uint(o1);
            s += sgf[2 * m] * o0 + sgf[2 * m + 1] * o1;
        }
        ls[ii] = s;
    }
    // reduce linear sums over the 16-thread tc group
    #pragma unroll
    for (int ii = 0; ii < 4; ii++) {
        float s = ls[ii];
        #pragma unroll
        for (int off = 8; off; off >>= 1) s += __shfl_xor_sync(0xffffffffu, s, off);
        if (tc == 0) {
            int row = bh * T + r0 + ti * 4 + ii;
            if (isk) g_Lk[row] = s; else g_Lq[row] = s;
        }
    }
    __syncthreads();

    // coalesced pair-major writeout
    ull* dst = (isk ? g_ksp : g_qsp) + (size_t)bh * NP * T;
    for (int idx = tid; idx < 64 * NP; idx += 256) {
        int r = idx & 63, p = idx >> 6;
        dst[p * T + r0 + r] = sT[r * 65 + p];
    }
}

// ---------------- K3: pairwise |.| main kernel (sign-sorted, 3-instr body) ----------------
// 1024 thr, 64x256 tile, split-half smem (conflict-free LDS.128).
constexpr int SM3_BYTES = 2048 * 8 * 2 + 8192 * 8 * 2 + 16 * 4;   // 163904

__global__ __launch_bounds__(1024, 1) void k3_main(
    const float* __restrict__ W2, const float* __restrict__ b2,
    float* __restrict__ out)
{
    extern __shared__ ull sm3[];
    ull* sq_lo = sm3;                 // [p][g<16] rows 4g+0,1   (2048 ull)
    ull* sq_hi = sq_lo + 2048;        // [p][g<16] rows 4g+2,3
    ull* sk_lo = sq_hi + 2048;        // [p][g<64] cols 4g+0,1   (8192 ull)
    ull* sk_hi = sk_lo + 8192;        // [p][g<64] cols 4g+2,3
    int* sCnt  = (int*)(sk_hi + 8192);   // [4]

    int tid = threadIdx.x;
    int bx  = blockIdx.x;
    int bh  = bx >> 4;
    int it  = (bx >> 1) & 7;
    int jt  = bx & 1;
    int i0  = it * 64, j0 = jt * 256;

    // positive-channel counts (warps 0-3)
    if (tid < 128) {
        uint wb = __float_as_uint(W2[tid]);
        uint bal = __ballot_sync(0xffffffffu, !(wb >> 31));
        if ((tid & 31) == 0) sCnt[tid >> 5] = __popc(bal);
    }

    const ull* gq = g_qsp + (size_t)bh * NP * T;
    const ull* gk = g_ksp + (size_t)bh * NP * T;

    // fills: gmem-coalesced reads; split-half smem writes (conflict-free)
    for (int idx = tid; idx < NP * 64; idx += 1024) {
        int p = idx >> 6, r = idx & 63;
        int g = r >> 2, h = (r >> 1) & 1, c = r & 1;
        (h ? sq_hi : sq_lo)[(p * 16 + g) * 2 + c] = gq[p * T + i0 + r];
    }
    for (int idx = tid; idx < NP * 256; idx += 1024) {
        int p = idx >> 8, j = idx & 255;
        int g = j >> 2, h = (j >> 1) & 1, c = j & 1;
        (h ? sk_hi : sk_lo)[(p * 64 + g) * 2 + c] = gk[p * T + j0 + j];
    }
    __syncthreads();

    int NPOS  = sCnt[0] + sCnt[1] + sCnt[2] + sCnt[3];
    int PA    = NPOS >> 1;          // full-positive pairs [0, PA)
    int mixed = NPOS & 1;           // one mixed pair at PA if odd
    int PN0   = PA + mixed;         // full-negative pairs [PN0, 64)

    int warp = tid >> 5, lane = tid & 31;
    int wi = warp >> 3, wj = warp & 7;   // 4x8 warps: warp tile 16x32
    int li = lane >> 3, lj = lane & 7;   // lanes: 4 row-groups x 8 col-groups

    int qg = wi * 4 + li;                // q group (rows 4qg..4qg+3)
    int kg = wj * 8 + lj;                // k group (cols 4kg..4kg+3)

    const ull* qlo = sq_lo + qg * 2;     // + p*32
    const ull* qhi = sq_hi + qg * 2;
    const ull* klo = sk_lo + kg * 2;     // + p*128
    const ull* khi = sk_hi + kg * 2;

    float accL[4][4], accH[4][4];
    #pragma unroll
    for (int r = 0; r < 4; r++)
        #pragma unroll
        for (int s = 0; s < 4; s++) { accL[r][s] = 0.0f; accH[r][s] = 0.0f; }

#define K3_LOADS(p)                                                      \
    ulonglong2 qv01 = *(const ulonglong2*)(qlo + (p) * 32);              \
    ulonglong2 qv23 = *(const ulonglong2*)(qhi + (p) * 32);              \
    ulonglong2 kv01 = *(const ulonglong2*)(klo + (p) * 128);             \
    ulonglong2 kv23 = *(const ulonglong2*)(khi + (p) * 128);             \
    ull qv[4] = { qv01.x, qv01.y, qv23.x, qv23.y };                      \
    ull kv[4] = { kv01.x, kv01.y, kv23.x, kv23.y };

    // ---- positive pairs: acc += |t| (abs folds into FADD operand modifier) ----
    #pragma unroll 1
    for (int p = 0; p < PA; p++) {
        K3_LOADS(p);
        #pragma unroll
        for (int r = 0; r < 4; r++)
            #pragma unroll
            for (int s = 0; s < 4; s++) {
                ull t;
                asm("add.rn.f32x2 %0, %1, %2;" : "=l"(t) : "l"(qv[r]), "l"(kv[s]));
                accL[r][s] += fabsf(__uint_as_float((uint)t));
                accH[r][s] += fabsf(__uint_as_float((uint)(t >> 32)));
            }
    }

    // ---- mixed pair (lo positive, hi negative) ----
    if (mixed) {
        K3_LOADS(PA);
        #pragma unroll
        for (int r = 0; r < 4; r++)
            #pragma unroll
            for (int s = 0; s < 4; s++) {
                ull t;
                asm("add.rn.f32x2 %0, %1, %2;" : "=l"(t) : "l"(qv[r]), "l"(kv[s]));
                accL[r][s] += fabsf(__uint_as_float((uint)t));
                accH[r][s] -= fabsf(__uint_as_float((uint)(t >> 32)));
            }
    }

    // ---- negative pairs: acc -= |t| ----
    #pragma unroll 1
    for (int p = PN0; p < NP; p++) {
        K3_LOADS(p);
        #pragma unroll
        for (int r = 0; r < 4; r++)
            #pragma unroll
            for (int s = 0; s < 4; s++) {
                ull t;
                asm("add.rn.f32x2 %0, %1, %2;" : "=l"(t) : "l"(qv[r]), "l"(kv[s]));
                accL[r][s] -= fabsf(__uint_as_float((uint)t));
                accH[r][s] -= fabsf(__uint_as_float((uint)(t >> 32)));
            }
    }
#undef K3_LOADS

    // epilogue: out = accL + accH + Lq_i + Lk_j + b2
    float b2v = b2[0];
    float4 Lq4 = *(const float4*)&g_Lq[bh * T + i0 + 4 * qg];
    float4 Lk4 = *(const float4*)&g_Lk[bh * T + j0 + 4 * kg];
    float Lqr[4] = { Lq4.x + b2v, Lq4.y + b2v, Lq4.z + b2v, Lq4.w + b2v };
    float Lks[4] = { Lk4.x, Lk4.y, Lk4.z, Lk4.w };

    float* ob = out + (size_t)(bh * T + i0 + 4 * qg) * T + j0 + 4 * kg;
    #pragma unroll
    for (int r = 0; r < 4; r++) {
        float4 v;
        float* vp = (float*)&v;
        #pragma unroll
        for (int s = 0; s < 4; s++)
            vp[s] = accL[r][s] + accH[r][s] + Lqr[r] + Lks[s];
        *(float4*)(ob + (size_t)r * T) = v;
    }
}

// ---------------- launch ----------------
extern "C" void kernel_launch(void* const* d_in, const int* in_sizes, int n_in,
                              void* d_out, int out_size) {
    const float* q  = (const float*)d_in[0];
    const float* k  = (const float*)d_in[1];
    const float* W1 = (const float*)d_in[2];
    const float* b1 = (const float*)d_in[3];
    const float* W2 = (const float*)d_in[4];
    const float* b2 = (const float*)d_in[5];
    float* out = (float*)d_out;

    cudaFuncSetAttribute(k1_proj, cudaFuncAttributeMaxDynamicSharedMemorySize, SM1_BYTES);
    cudaFuncSetAttribute(k3_main, cudaFuncAttributeMaxDynamicSharedMemorySize, SM3_BYTES);

    k1_proj<<<dim3(8, BH, 2), 256, SM1_BYTES>>>(q, k, W1, b1, W2);
    k3_main<<<128, 1024, SM3_BYTES>>>(W2, b2, out);
}